// round 4
// baseline (speedup 1.0000x reference)
#include <cuda_runtime.h>
#include <math.h>

#define Bb 8
#define Nn 1024
#define Qq 256
#define Dd 8
#define Mm (Nn + Qq)            // 1280
#define M_PER_BLOCK 8
#define NSPLIT 16
#define THREADS (M_PER_BLOCK * NSPLIT)   // 128
#define N_PER_THREAD (Nn / NSPLIT)       // 64
#define LN_EPS 1e-5f

__device__ __forceinline__ float ex2_fast(float x) {
    float y;
    asm("ex2.approx.ftz.f32 %0, %1;" : "=f"(y) : "f"(x));
    return y;
}

__global__ __launch_bounds__(THREADS, 10) void skpe_kernel(
    const float* __restrict__ lm_s,   // [B,N]
    const float* __restrict__ ttm_s,  // [B,N]
    const float* __restrict__ tv_s,   // [B,N]
    const float* __restrict__ lm_q,   // [B,Q]
    const float* __restrict__ ttm_q,  // [B,Q]
    const float* __restrict__ kls,    // [D,2]
    const float* __restrict__ g_s,    // [D]
    const float* __restrict__ be_s,   // [D]
    const float* __restrict__ g_q,    // [D]
    const float* __restrict__ be_q,   // [D]
    const float* __restrict__ pe_ls,  // [1]
    float* __restrict__ out)          // [B*N*D + B*Q*D]
{
    __shared__ float4 s4[Nn];         // (x, y, v, pad)  16KB
    __shared__ float sA[Dd], sB[Dd];
    __shared__ int sUniform;

    const int blocks_per_batch = Mm / M_PER_BLOCK;   // 160
    const int b  = blockIdx.x / blocks_per_batch;
    const int mt = blockIdx.x % blocks_per_batch;
    const int tid = threadIdx.x;

    // Stage this batch's sources into shared (packed)
    #pragma unroll
    for (int i = tid; i < Nn; i += THREADS) {
        s4[i] = make_float4(lm_s[b * Nn + i], ttm_s[b * Nn + i], tv_s[b * Nn + i], 0.0f);
    }

    // Per-channel exponent coefficients (with -log2(e) folded in): computed once
    const float LOG2E = 1.4426950408889634f;
    const float SQRT2 = 1.4142135623730951f;
    if (tid == 0) sUniform = 1;
    __syncthreads();
    if (tid < Dd) {
        int d = tid;
        float s0 = __expf(kls[2 * d + 0]);
        float s1 = __expf(kls[2 * d + 1]);
        float tr = s0 + s1;
        float fr = (float)(d + 1) / (float)(Dd + 1);
        float bw = erfinvf(fr) * SQRT2;
        float inv = LOG2E / (tr * 2.0f * bw * bw);
        sA[d] = -s0 * inv;
        sB[d] = -s1 * inv;
        if (__float_as_uint(-s0 * inv) != __float_as_uint(-s1 * inv))
            atomicAnd(&sUniform, 0);
    }
    __syncthreads();

    const bool uniform = (sUniform != 0);

    const int s  = tid & (NSPLIT - 1);     // n-split id, 0..15
    const int ml = tid >> 4;               // local m, 0..7
    const int m  = mt * M_PER_BLOCK + ml;  // m within batch, 0..1279

    float xm, ym;
    if (m < Nn) { float4 p = s4[m]; xm = p.x; ym = p.y; }
    else        { xm = lm_q[b * Qq + (m - Nn)]; ym = ttm_q[b * Qq + (m - Nn)]; }

    float wa[Dd], na[Dd];
    #pragma unroll
    for (int d = 0; d < Dd; d++) { wa[d] = 0.0f; na[d] = 0.0f; }

    if (uniform) {
        // Fast path: A[d] == B[d] bitwise -> exponent arg = (dx^2+dy^2) * A[d]
        float A[Dd];
        #pragma unroll
        for (int d = 0; d < Dd; d++) A[d] = sA[d];

        #pragma unroll 8
        for (int k = 0; k < N_PER_THREAD; k++) {
            int n = k * NSPLIT + s;
            float4 p = s4[n];
            float dx = xm - p.x;
            float dy = ym - p.y;
            float tv = p.z;
            float t = fmaf(dy, dy, dx * dx);
            #pragma unroll
            for (int d = 0; d < Dd; d++) {
                float e = ex2_fast(t * A[d]);
                wa[d] = fmaf(e, tv, wa[d]);
                na[d] += e;
            }
        }
    } else {
        // General path: independent per-axis scales (coefficients read from
        // shared per use to keep register pressure off the fast path)
        #pragma unroll 2
        for (int k = 0; k < N_PER_THREAD; k++) {
            int n = k * NSPLIT + s;
            float4 p = s4[n];
            float dx = xm - p.x;
            float dy = ym - p.y;
            float tv = p.z;
            float dx2 = dx * dx;
            float dy2 = dy * dy;
            #pragma unroll
            for (int d = 0; d < Dd; d++) {
                volatile const float* vA = sA;
                volatile const float* vB = sB;
                float e = ex2_fast(fmaf(dx2, vA[d], dy2 * vB[d]));
                wa[d] = fmaf(e, tv, wa[d]);
                na[d] += e;
            }
        }
    }

    // Butterfly reduce across the 16 n-splits (stays within 16-lane groups)
    #pragma unroll
    for (int off = 1; off < NSPLIT; off <<= 1) {
        #pragma unroll
        for (int d = 0; d < Dd; d++) {
            wa[d] += __shfl_xor_sync(0xFFFFFFFFu, wa[d], off);
            na[d] += __shfl_xor_sync(0xFFFFFFFFu, na[d], off);
        }
    }

    if (s == 0) {
        float emb[Dd];
        float mu = 0.0f;
        #pragma unroll
        for (int d = 0; d < Dd; d++) {
            emb[d] = wa[d] / na[d];
            mu += emb[d];
        }
        mu *= (1.0f / Dd);
        float var = 0.0f;
        #pragma unroll
        for (int d = 0; d < Dd; d++) {
            float t = emb[d] - mu;
            var = fmaf(t, t, var);
        }
        var *= (1.0f / Dd);
        float rstd = rsqrtf(var + LN_EPS);

        const bool is_src = (m < Nn);
        const float* g  = is_src ? g_s  : g_q;
        const float* be = is_src ? be_s : be_q;

        // Positional embedding
        float pls = pe_ls[0];
        float pe[Dd];
        #pragma unroll
        for (int i = 0; i < Dd / 4; i++) {
            float invdiv = __expf(-pls * (4.0f * (float)i / (float)Dd));
            float ax = xm * invdiv;
            float ay = ym * invdiv;
            pe[4 * i + 0] = __sinf(ax);
            pe[4 * i + 1] = __cosf(ax);
            pe[4 * i + 2] = __sinf(ay);
            pe[4 * i + 3] = __cosf(ay);
        }

        float* outp;
        if (is_src) outp = out + ((size_t)b * Nn + m) * Dd;
        else        outp = out + (size_t)Bb * Nn * Dd + ((size_t)b * Qq + (m - Nn)) * Dd;

        #pragma unroll
        for (int d = 0; d < Dd; d++) {
            outp[d] = (emb[d] - mu) * rstd * g[d] + be[d] + pe[d] * SQRT2;
        }
    }
}

extern "C" void kernel_launch(void* const* d_in, const int* in_sizes, int n_in,
                              void* d_out, int out_size) {
    const float* lm_s   = (const float*)d_in[0];
    const float* ttm_s  = (const float*)d_in[1];
    const float* tv_s   = (const float*)d_in[2];
    const float* lm_q   = (const float*)d_in[3];
    const float* ttm_q  = (const float*)d_in[4];
    const float* kls    = (const float*)d_in[5];
    const float* g_s    = (const float*)d_in[6];
    const float* be_s   = (const float*)d_in[7];
    const float* g_q    = (const float*)d_in[8];
    const float* be_q   = (const float*)d_in[9];
    const float* pe_ls  = (const float*)d_in[10];
    float* out = (float*)d_out;

    dim3 grid(Bb * (Mm / M_PER_BLOCK));  // 1280 blocks
    dim3 block(THREADS);                 // 128 threads
    skpe_kernel<<<grid, block>>>(lm_s, ttm_s, tv_s, lm_q, ttm_q, kls,
                                 g_s, be_s, g_q, be_q, pe_ls, out);
}

// round 5
// speedup vs baseline: 1.0067x; 1.0067x over previous
#include <cuda_runtime.h>
#include <math.h>

#define Bb 8
#define Nn 1024
#define Qq 256
#define Dd 8
#define Mm (Nn + Qq)            // 1280
#define M_PER_BLOCK 8
#define NSPLIT 16
#define THREADS (M_PER_BLOCK * NSPLIT)   // 128
#define N_PER_THREAD (Nn / NSPLIT)       // 64
#define LN_EPS 1e-5f

__device__ __forceinline__ float ex2_fast(float x) {
    float y;
    asm("ex2.approx.ftz.f32 %0, %1;" : "=f"(y) : "f"(x));
    return y;
}

__global__ __launch_bounds__(THREADS, 10) void skpe_kernel(
    const float* __restrict__ lm_s,   // [B,N]
    const float* __restrict__ ttm_s,  // [B,N]
    const float* __restrict__ tv_s,   // [B,N]
    const float* __restrict__ lm_q,   // [B,Q]
    const float* __restrict__ ttm_q,  // [B,Q]
    const float* __restrict__ kls,    // [D,2]
    const float* __restrict__ g_s,    // [D]
    const float* __restrict__ be_s,   // [D]
    const float* __restrict__ g_q,    // [D]
    const float* __restrict__ be_q,   // [D]
    const float* __restrict__ pe_ls,  // [1]
    float* __restrict__ out)          // [B*N*D + B*Q*D]
{
    __shared__ float4 s4[Nn];         // (x, y, v, pad)  16KB
    __shared__ float sA[Dd], sB[Dd];
    __shared__ int sUniform;

    const int blocks_per_batch = Mm / M_PER_BLOCK;   // 160
    const int b  = blockIdx.x / blocks_per_batch;
    const int mt = blockIdx.x % blocks_per_batch;
    const int tid = threadIdx.x;

    // Stage this batch's sources into shared (packed)
    #pragma unroll
    for (int i = tid; i < Nn; i += THREADS) {
        s4[i] = make_float4(lm_s[b * Nn + i], ttm_s[b * Nn + i], tv_s[b * Nn + i], 0.0f);
    }

    // Per-channel exponent coefficients (with -log2(e) folded in): computed once
    const float LOG2E = 1.4426950408889634f;
    const float SQRT2 = 1.4142135623730951f;
    if (tid == 0) sUniform = 1;
    __syncthreads();
    if (tid < Dd) {
        int d = tid;
        float s0 = __expf(kls[2 * d + 0]);
        float s1 = __expf(kls[2 * d + 1]);
        float tr = s0 + s1;
        float fr = (float)(d + 1) / (float)(Dd + 1);
        float bw = erfinvf(fr) * SQRT2;
        float inv = LOG2E / (tr * 2.0f * bw * bw);
        sA[d] = -s0 * inv;
        sB[d] = -s1 * inv;
        if (__float_as_uint(-s0 * inv) != __float_as_uint(-s1 * inv))
            atomicAnd(&sUniform, 0);
    }
    __syncthreads();

    const bool uniform = (sUniform != 0);

    const int s  = tid & (NSPLIT - 1);     // n-split id, 0..15
    const int ml = tid >> 4;               // local m, 0..7
    const int m  = mt * M_PER_BLOCK + ml;  // m within batch, 0..1279

    float xm, ym;
    if (m < Nn) { float4 p = s4[m]; xm = p.x; ym = p.y; }
    else        { xm = lm_q[b * Qq + (m - Nn)]; ym = ttm_q[b * Qq + (m - Nn)]; }

    float wa[Dd], na[Dd];
    #pragma unroll
    for (int d = 0; d < Dd; d++) { wa[d] = 0.0f; na[d] = 0.0f; }

    if (uniform) {
        // Fast path: A[d] == B[d] bitwise -> exponent arg = (dx^2+dy^2) * A[d]
        float A[Dd];
        #pragma unroll
        for (int d = 0; d < Dd; d++) A[d] = sA[d];

        #pragma unroll 8
        for (int k = 0; k < N_PER_THREAD; k++) {
            int n = k * NSPLIT + s;
            float4 p = s4[n];
            float dx = xm - p.x;
            float dy = ym - p.y;
            float tv = p.z;
            float t = fmaf(dy, dy, dx * dx);
            #pragma unroll
            for (int d = 0; d < Dd; d++) {
                float e = ex2_fast(t * A[d]);
                wa[d] = fmaf(e, tv, wa[d]);
                na[d] += e;
            }
        }
    } else {
        // General path: independent per-axis scales (coefficients read from
        // shared per use to keep register pressure off the fast path)
        #pragma unroll 2
        for (int k = 0; k < N_PER_THREAD; k++) {
            int n = k * NSPLIT + s;
            float4 p = s4[n];
            float dx = xm - p.x;
            float dy = ym - p.y;
            float tv = p.z;
            float dx2 = dx * dx;
            float dy2 = dy * dy;
            #pragma unroll
            for (int d = 0; d < Dd; d++) {
                volatile const float* vA = sA;
                volatile const float* vB = sB;
                float e = ex2_fast(fmaf(dx2, vA[d], dy2 * vB[d]));
                wa[d] = fmaf(e, tv, wa[d]);
                na[d] += e;
            }
        }
    }

    // Butterfly reduce across the 16 n-splits (stays within 16-lane groups)
    #pragma unroll
    for (int off = 1; off < NSPLIT; off <<= 1) {
        #pragma unroll
        for (int d = 0; d < Dd; d++) {
            wa[d] += __shfl_xor_sync(0xFFFFFFFFu, wa[d], off);
            na[d] += __shfl_xor_sync(0xFFFFFFFFu, na[d], off);
        }
    }

    if (s == 0) {
        float emb[Dd];
        float mu = 0.0f;
        #pragma unroll
        for (int d = 0; d < Dd; d++) {
            emb[d] = wa[d] / na[d];
            mu += emb[d];
        }
        mu *= (1.0f / Dd);
        float var = 0.0f;
        #pragma unroll
        for (int d = 0; d < Dd; d++) {
            float t = emb[d] - mu;
            var = fmaf(t, t, var);
        }
        var *= (1.0f / Dd);
        float rstd = rsqrtf(var + LN_EPS);

        const bool is_src = (m < Nn);
        const float* g  = is_src ? g_s  : g_q;
        const float* be = is_src ? be_s : be_q;

        // Positional embedding
        float pls = pe_ls[0];
        float pe[Dd];
        #pragma unroll
        for (int i = 0; i < Dd / 4; i++) {
            float invdiv = __expf(-pls * (4.0f * (float)i / (float)Dd));
            float ax = xm * invdiv;
            float ay = ym * invdiv;
            pe[4 * i + 0] = __sinf(ax);
            pe[4 * i + 1] = __cosf(ax);
            pe[4 * i + 2] = __sinf(ay);
            pe[4 * i + 3] = __cosf(ay);
        }

        float* outp;
        if (is_src) outp = out + ((size_t)b * Nn + m) * Dd;
        else        outp = out + (size_t)Bb * Nn * Dd + ((size_t)b * Qq + (m - Nn)) * Dd;

        #pragma unroll
        for (int d = 0; d < Dd; d++) {
            outp[d] = (emb[d] - mu) * rstd * g[d] + be[d] + pe[d] * SQRT2;
        }
    }
}

extern "C" void kernel_launch(void* const* d_in, const int* in_sizes, int n_in,
                              void* d_out, int out_size) {
    const float* lm_s   = (const float*)d_in[0];
    const float* ttm_s  = (const float*)d_in[1];
    const float* tv_s   = (const float*)d_in[2];
    const float* lm_q   = (const float*)d_in[3];
    const float* ttm_q  = (const float*)d_in[4];
    const float* kls    = (const float*)d_in[5];
    const float* g_s    = (const float*)d_in[6];
    const float* be_s   = (const float*)d_in[7];
    const float* g_q    = (const float*)d_in[8];
    const float* be_q   = (const float*)d_in[9];
    const float* pe_ls  = (const float*)d_in[10];
    float* out = (float*)d_out;

    // Ask for the maximum shared-memory carveout so 10 blocks/SM (164KB smem)
    // can be co-resident. Idempotent host-side attribute set; no allocation,
    // no stream work — safe under graph capture.
    cudaFuncSetAttribute(skpe_kernel,
                         cudaFuncAttributePreferredSharedMemoryCarveout,
                         cudaSharedmemCarveoutMaxShared);

    dim3 grid(Bb * (Mm / M_PER_BLOCK));  // 1280 blocks
    dim3 block(THREADS);                 // 128 threads
    skpe_kernel<<<grid, block>>>(lm_s, ttm_s, tv_s, lm_q, ttm_q, kls,
                                 g_s, be_s, g_q, be_q, pe_ls, out);
}